// round 6
// baseline (speedup 1.0000x reference)
#include <cuda_runtime.h>
#include <cstdint>

#define NN      50000
#define EE      800000
#define EF      (EE + NN)
#define HH      128
#define LATD    64
#define MAXNODE 200
#define ADJ_SZ   (NN * MAXNODE)
#define NODES_SZ (NN * HH)
#define MU_OFF   (ADJ_SZ + NODES_SZ)
#define LV_OFF   (MU_OFF + LATD)
#define HG_BLOCKS 512

// ---- scratch: static device globals (no allocation). NEVER passed from host. ----
__device__ __align__(16) static int   g_src[EE];
__device__ __align__(16) static int   g_dst[EE];
__device__ __align__(16) static float g_eterm1[EE];
__device__ __align__(16) static float g_eterm2[EE];
__device__ __align__(16) static float g_deg[NN];
__device__ __align__(16) static float g_set1[NN];
__device__ __align__(16) static float g_set2[NN];
__device__ __align__(16) static float g_ve[32];
__device__ __align__(16) static float g_g[2][(size_t)NN * HH];
__device__ __align__(16) static float g_agg[2][(size_t)NN * HH];
__device__ __align__(16) static float g_gs[2][NN];
__device__ __align__(16) static float g_gd[2][NN];
__device__ __align__(16) static float g_den[2][NN];
__device__ __align__(16) static float g_ex[EF];
__device__ __align__(16) static float g_hpart[HG_BLOCKS * HH];
__device__ __align__(16) static float g_adj_row[MAXNODE];
__device__ __align__(16) static float g_node_row[HH];
__device__ static int g_idx64;

// relu that PROPAGATES NaN (fmaxf would launder NaN to 0 and hide failures)
__device__ __forceinline__ float relu_np(float v) { return v * (float)(v > 0.f); }

__global__ void k_zero() {
    int stride = gridDim.x * blockDim.x;
    int i0 = blockIdx.x * blockDim.x + threadIdx.x;
    for (int j = i0; j < NN * HH; j += stride) { g_agg[0][j] = 0.f; g_agg[1][j] = 0.f; }
    for (int j = i0; j < NN; j += stride) {
        g_deg[j] = 0.f; g_set1[j] = 0.f; g_set2[j] = 0.f;
        g_den[0][j] = 0.f; g_den[1][j] = 0.f;
    }
}

__global__ void k_pre(const int* __restrict__ ei,
                      const float* __restrict__ We1, const float* __restrict__ ae1,
                      const float* __restrict__ We2, const float* __restrict__ ae2) {
    __shared__ int nz;
    if (threadIdx.x == 0) nz = 0;
    __syncthreads();
    for (int i = threadIdx.x; i < 1024; i += blockDim.x)
        if (ei[2 * i + 1] != 0) atomicAdd(&nz, 1);
    __syncthreads();
    if (threadIdx.x == 0) g_idx64 = (nz == 0) ? 1 : 0;
    int k = threadIdx.x;
    if (k < 16) {
        float s = 0.f;
        for (int h = 0; h < HH; h++) s += We1[k * HH + h] * ae1[h];
        g_ve[k] = s;
    } else if (k < 32) {
        int kk = k - 16;
        float s = 0.f;
        for (int h = 0; h < HH; h++) s += We2[kk * HH + h] * ae2[h];
        g_ve[16 + kk] = s;
    }
}

__global__ void k_edges(const int* __restrict__ ei_raw, const float* __restrict__ ea) {
    __shared__ float sve[32];
    if (threadIdx.x < 32) sve[threadIdx.x] = g_ve[threadIdx.x];
    __syncthreads();
    int stride = gridDim.x * blockDim.x;
    int idx64 = g_idx64;
    for (int e = blockIdx.x * blockDim.x + threadIdx.x; e < EE; e += stride) {
        int src, dst;
        if (idx64) {
            const long long* pp = (const long long*)ei_raw;
            src = (int)pp[e]; dst = (int)pp[EE + e];
        } else {
            src = ei_raw[e]; dst = ei_raw[EE + e];
        }
        g_src[e] = src; g_dst[e] = dst;
        const float* eav = ea + (size_t)e * 16;
        float t1 = 0.f, t2 = 0.f;
#pragma unroll
        for (int q = 0; q < 16; q++) {
            float v = eav[q];
            t1 += v * sve[q];
            t2 += v * sve[16 + q];
        }
        g_eterm1[e] = t1; g_eterm2[e] = t2;
        atomicAdd(&g_set1[dst], t1);
        atomicAdd(&g_set2[dst], t2);
        atomicAdd(&g_deg[dst], 1.0f);
    }
}

__global__ void k_loopdiv() {
    int i = blockIdx.x * blockDim.x + threadIdx.x;
    if (i >= NN) return;
    float d = fmaxf(g_deg[i], 1.0f);
    g_set1[i] /= d;
    g_set2[i] /= d;
}

// layer 0: g_g[0] = x @ W          (x passed as input pointer - genuine device mem)
// layer 1: g_g[1] = relu(g_agg[0] + bias) @ W
// Scratch arrays resolved DEVICE-SIDE (host cannot take __device__ symbol addresses).
__global__ void __launch_bounds__(256) k_gemm128(int layer,
                                                 const float* __restrict__ x,
                                                 const float* __restrict__ W,
                                                 const float* __restrict__ bias) {
    __shared__ float4 Ws4[64 * 32];
    const float* A = (layer == 0) ? x : g_agg[0];
    float*       C = g_g[layer];
    int tid  = threadIdx.x;
    int warp = tid >> 5, lane = tid & 31;
    int row0 = blockIdx.x * 32 + warp * 4;

    float4 bsel = make_float4(0.f, 0.f, 0.f, 0.f);
    if (layer == 1) bsel = ((const float4*)bias)[lane];

    float4 av[4];
#pragma unroll
    for (int r = 0; r < 4; r++) {
        int row = row0 + r;
        float4 v = make_float4(0.f, 0.f, 0.f, 0.f);
        if (row < NN) {
            v = ((const float4*)A)[(size_t)row * 32 + lane];
            if (layer == 1) {
                v.x = relu_np(v.x + bsel.x);
                v.y = relu_np(v.y + bsel.y);
                v.z = relu_np(v.z + bsel.z);
                v.w = relu_np(v.w + bsel.w);
            }
        }
        av[r] = v;
    }

    float4 acc[4];
#pragma unroll
    for (int r = 0; r < 4; r++) acc[r] = make_float4(0.f, 0.f, 0.f, 0.f);

#pragma unroll
    for (int chunk = 0; chunk < 2; chunk++) {
        const float4* Wc = (const float4*)W + chunk * 64 * 32;
        __syncthreads();
        for (int i = tid; i < 64 * 32; i += 256) Ws4[i] = Wc[i];
        __syncthreads();
#pragma unroll
        for (int kk = 0; kk < 64; kk++) {
            int k = chunk * 64 + kk;
            int srcLane = k >> 2;
            const int sel = k & 3;
            float4 w4 = Ws4[kk * 32 + lane];
#pragma unroll
            for (int r = 0; r < 4; r++) {
                float av_sel = (sel == 0) ? av[r].x : (sel == 1) ? av[r].y
                             : (sel == 2) ? av[r].z : av[r].w;
                float a_k = __shfl_sync(0xffffffffu, av_sel, srcLane);
                acc[r].x += a_k * w4.x;
                acc[r].y += a_k * w4.y;
                acc[r].z += a_k * w4.z;
                acc[r].w += a_k * w4.w;
            }
        }
    }

#pragma unroll
    for (int r = 0; r < 4; r++) {
        int row = row0 + r;
        if (row < NN)
            ((float4*)C)[(size_t)row * 32 + lane] = acc[r];
    }
}

__global__ void k_gsgd(int layer, const float* __restrict__ as, const float* __restrict__ ad) {
    int gt = blockIdx.x * blockDim.x + threadIdx.x;
    int row = gt >> 5, lane = gt & 31;
    if (row >= NN) return;
    const float* gp = g_g[layer];
    float4 v = *(const float4*)(gp + (size_t)row * HH + lane * 4);
    float4 s4 = ((const float4*)as)[lane];
    float4 d4 = ((const float4*)ad)[lane];
    float s = v.x * s4.x + v.y * s4.y + v.z * s4.z + v.w * s4.w;
    float d = v.x * d4.x + v.y * d4.y + v.z * d4.z + v.w * d4.w;
#pragma unroll
    for (int off = 16; off > 0; off >>= 1) {
        s += __shfl_xor_sync(0xFFFFFFFFu, s, off);
        d += __shfl_xor_sync(0xFFFFFFFFu, d, off);
    }
    if (lane == 0) {
        g_gs[layer][row] = s;
        g_gd[layer][row] = d;
    }
}

// single-pass softmax numerator: alpha is O(1) so exp without max-shift is exact
__global__ void k_alpha(int layer) {
    int stride = gridDim.x * blockDim.x;
    const float* gs = g_gs[layer];
    const float* gd = g_gd[layer];
    const float* et1 = layer ? g_eterm2 : g_eterm1;
    const float* set = layer ? g_set2 : g_set1;
    float* den = g_den[layer];
    for (int e = blockIdx.x * blockDim.x + threadIdx.x; e < EF; e += stride) {
        int src, dst; float et;
        if (e < EE) {
            src = g_src[e]; dst = g_dst[e];
            et = et1[e];
        } else {
            src = dst = e - EE;
            et = set[src];
        }
        float a = gs[src] + gd[dst] + et;
        a = a > 0.f ? a : 0.2f * a;
        float ex = expf(a);
        g_ex[e] = ex;
        atomicAdd(&den[dst], ex);
    }
}

// agg[dst] += (ex/den[dst]) * g[src]   (one warp/edge, grid-stride, scalar atomics)
__global__ void k_agg(int layer) {
    int warps = (gridDim.x * blockDim.x) >> 5;
    int w0 = (blockIdx.x * blockDim.x + threadIdx.x) >> 5;
    int lane = threadIdx.x & 31;
    const float* gp  = g_g[layer];
    const float* den = g_den[layer];
    float* aggp      = g_agg[layer];
    for (int e = w0; e < EF; e += warps) {
        int src, dst;
        if (e < EE) { src = g_src[e]; dst = g_dst[e]; }
        else        { src = dst = e - EE; }
        float w = g_ex[e] / den[dst];
        float4 v = *(const float4*)(gp + (size_t)src * HH + lane * 4);
        float* ap = aggp + (size_t)dst * HH + lane * 4;
        atomicAdd(ap + 0, w * v.x);
        atomicAdd(ap + 1, w * v.y);
        atomicAdd(ap + 2, w * v.z);
        atomicAdd(ap + 3, w * v.w);
    }
}

// deterministic per-block partials of sum_i relu(agg2[i][c] + b2[c])
__global__ void k_hgsum(const float* __restrict__ b2) {
    __shared__ float sh[HH];
    int c = threadIdx.x & 127;
    int half = threadIdx.x >> 7;
    float bb = b2[c];
    float s = 0.f;
    for (int i = blockIdx.x * 2 + half; i < NN; i += gridDim.x * 2)
        s += relu_np(g_agg[1][(size_t)i * HH + c] + bb);
    if (half == 1) sh[c] = s;
    __syncthreads();
    if (half == 0) g_hpart[blockIdx.x * HH + c] = s + sh[c];
}

__global__ void k_head(const float* __restrict__ muW, const float* __restrict__ mub,
                       const float* __restrict__ lvW, const float* __restrict__ lvb,
                       const float* __restrict__ eps,
                       const float* __restrict__ decW, const float* __restrict__ decb,
                       const float* __restrict__ aW1, const float* __restrict__ ab1,
                       const float* __restrict__ aW2, const float* __restrict__ ab2,
                       const float* __restrict__ nW1, const float* __restrict__ nb1,
                       const float* __restrict__ nW2, const float* __restrict__ nb2,
                       float* __restrict__ out) {
    __shared__ float hgm[HH], z[LATD], hd[HH], tmp[HH];
    int t = threadIdx.x;
    if (t < HH) {
        float s = 0.f;
        for (int b = 0; b < HG_BLOCKS; b++) s += g_hpart[b * HH + t];
        hgm[t] = s * (1.0f / (float)NN);
    }
    __syncthreads();
    if (t < LATD) {
        float m = mub[t], l = lvb[t];
        for (int k = 0; k < HH; k++) { m += hgm[k] * muW[k * LATD + t]; l += hgm[k] * lvW[k * LATD + t]; }
        out[MU_OFF + t] = m;
        out[LV_OFF + t] = l;
        z[t] = m + eps[t] * expf(0.5f * l);
    }
    __syncthreads();
    if (t < HH) {
        float s = decb[t];
        for (int j = 0; j < LATD; j++) s += z[j] * decW[j * HH + t];
        hd[t] = relu_np(s);
    }
    __syncthreads();
    if (t < HH) {
        float s = ab1[t];
        for (int k = 0; k < HH; k++) s += hd[k] * aW1[k * HH + t];
        tmp[t] = relu_np(s);
    }
    __syncthreads();
    for (int m = t; m < MAXNODE; m += blockDim.x) {
        float s = ab2[m];
        for (int k = 0; k < HH; k++) s += tmp[k] * aW2[k * MAXNODE + m];
        g_adj_row[m] = s;
    }
    __syncthreads();
    if (t < HH) {
        float s = nb1[t];
        for (int k = 0; k < HH; k++) s += hd[k] * nW1[k * HH + t];
        tmp[t] = relu_np(s);
    }
    __syncthreads();
    if (t < HH) {
        float s = nb2[t];
        for (int k = 0; k < HH; k++) s += tmp[k] * nW2[k * HH + t];
        g_node_row[t] = s;
    }
}

__global__ void k_fill(float4* __restrict__ out4) {
    __shared__ float4 sadj[50];
    __shared__ float4 snd[32];
    int t = threadIdx.x;
    if (t < 50) sadj[t] = ((const float4*)g_adj_row)[t];
    else if (t < 82) snd[t - 50] = ((const float4*)g_node_row)[t - 50];
    __syncthreads();
    const int ADJ4 = ADJ_SZ / 4;
    const int TOT4 = (ADJ_SZ + NODES_SZ) / 4;
    int stride = gridDim.x * blockDim.x;
    for (int i = blockIdx.x * blockDim.x + t; i < TOT4; i += stride) {
        float4 v;
        if (i < ADJ4) v = sadj[i % 50];
        else          v = snd[(i - ADJ4) & 31];
        out4[i] = v;
    }
}

extern "C" void kernel_launch(void* const* d_in, const int* in_sizes, int n_in,
                              void* d_out, int out_size) {
    const float* x   = (const float*)d_in[0];
    const int*   ei  = (const int*)  d_in[1];
    const float* ea  = (const float*)d_in[2];
    const float* eps = (const float*)d_in[3];
    int p = n_in - 26;                 // 26 trailing weight tensors
    if (p < 4) p = 4;
    if (p > 5) p = (in_sizes[4] == 1) ? 5 : 4;
    const float* W1   = (const float*)d_in[p + 0];
    const float* as1  = (const float*)d_in[p + 1];
    const float* ad1  = (const float*)d_in[p + 2];
    const float* We1  = (const float*)d_in[p + 3];
    const float* ae1  = (const float*)d_in[p + 4];
    const float* b1   = (const float*)d_in[p + 5];
    const float* W2   = (const float*)d_in[p + 6];
    const float* as2  = (const float*)d_in[p + 7];
    const float* ad2  = (const float*)d_in[p + 8];
    const float* We2  = (const float*)d_in[p + 9];
    const float* ae2  = (const float*)d_in[p + 10];
    const float* b2   = (const float*)d_in[p + 11];
    const float* muW  = (const float*)d_in[p + 12];
    const float* mub  = (const float*)d_in[p + 13];
    const float* lvW  = (const float*)d_in[p + 14];
    const float* lvb  = (const float*)d_in[p + 15];
    const float* decW = (const float*)d_in[p + 16];
    const float* decb = (const float*)d_in[p + 17];
    const float* aW1  = (const float*)d_in[p + 18];
    const float* ab1  = (const float*)d_in[p + 19];
    const float* aW2  = (const float*)d_in[p + 20];
    const float* ab2  = (const float*)d_in[p + 21];
    const float* nW1  = (const float*)d_in[p + 22];
    const float* nb1  = (const float*)d_in[p + 23];
    const float* nW2  = (const float*)d_in[p + 24];
    const float* nb2  = (const float*)d_in[p + 25];
    float* out = (float*)d_out;

    k_zero<<<2048, 256>>>();
    k_pre<<<1, 256>>>(ei, We1, ae1, We2, ae2);
    k_edges<<<2048, 256>>>(ei, ea);
    k_loopdiv<<<(NN + 255) / 256, 256>>>();

    int gemm_blocks = (NN + 31) / 32;
    int gsgd_blocks = (NN * 32 + 255) / 256;

    k_gemm128<<<gemm_blocks, 256>>>(0, x, W1, b1);
    k_gsgd<<<gsgd_blocks, 256>>>(0, as1, ad1);
    k_alpha<<<2048, 256>>>(0);
    k_agg<<<8192, 256>>>(0);

    k_gemm128<<<gemm_blocks, 256>>>(1, x, W2, b1);
    k_gsgd<<<gsgd_blocks, 256>>>(1, as2, ad2);
    k_alpha<<<2048, 256>>>(1);
    k_agg<<<8192, 256>>>(1);

    k_hgsum<<<HG_BLOCKS, 256>>>(b2);
    k_head<<<1, 256>>>(muW, mub, lvW, lvb, eps, decW, decb,
                       aW1, ab1, aW2, ab2, nW1, nb1, nW2, nb2, out);
    k_fill<<<2048, 256>>>((float4*)out);
}

// round 7
// speedup vs baseline: 2.0452x; 2.0452x over previous
#include <cuda_runtime.h>
#include <cstdint>

#define NN      50000
#define EE      800000
#define HH      128
#define LATD    64
#define MAXNODE 200
#define ADJ_SZ   (NN * MAXNODE)
#define NODES_SZ (NN * HH)
#define MU_OFF   (ADJ_SZ + NODES_SZ)
#define LV_OFF   (MU_OFF + LATD)
#define HG_BLOCKS 512

// ---- scratch: static device globals (no allocation). NEVER passed from host. ----
__device__ __align__(16) static int   g_src[EE];
__device__ __align__(16) static int   g_dst[EE];
__device__ __align__(16) static float g_eterm1[EE];
__device__ __align__(16) static float g_eterm2[EE];
__device__ __align__(16) static int   g_srcs[EE];    // CSR-sorted src
__device__ __align__(16) static float g_et1s[EE];    // CSR-sorted eterm1
__device__ __align__(16) static float g_et2s[EE];    // CSR-sorted eterm2
__device__ __align__(16) static int   g_rowptr[NN + 1];
__device__ __align__(16) static int   g_cursor[NN];
__device__ __align__(16) static float g_deg[NN];
__device__ __align__(16) static float g_set1[NN];
__device__ __align__(16) static float g_set2[NN];
__device__ __align__(16) static float g_ve[32];
__device__ __align__(16) static float g_g[2][(size_t)NN * HH];
__device__ __align__(16) static float g_agg[2][(size_t)NN * HH];
__device__ __align__(16) static float g_gs[2][NN];
__device__ __align__(16) static float g_gd[2][NN];
__device__ __align__(16) static float g_ex[EE];
__device__ __align__(16) static float g_hpart[HG_BLOCKS * HH];
__device__ __align__(16) static float g_adj_row[MAXNODE];
__device__ __align__(16) static float g_node_row[HH];
__device__ static int g_idx64;

__device__ __forceinline__ float relu_np(float v) { return v * (float)(v > 0.f); }

__global__ void k_zero() {
    int stride = gridDim.x * blockDim.x;
    int i0 = blockIdx.x * blockDim.x + threadIdx.x;
    for (int j = i0; j < NN; j += stride) {
        g_deg[j] = 0.f; g_set1[j] = 0.f; g_set2[j] = 0.f;
    }
}

__global__ void k_pre(const int* __restrict__ ei,
                      const float* __restrict__ We1, const float* __restrict__ ae1,
                      const float* __restrict__ We2, const float* __restrict__ ae2) {
    __shared__ int nz;
    if (threadIdx.x == 0) nz = 0;
    __syncthreads();
    for (int i = threadIdx.x; i < 1024; i += blockDim.x)
        if (ei[2 * i + 1] != 0) atomicAdd(&nz, 1);
    __syncthreads();
    if (threadIdx.x == 0) g_idx64 = (nz == 0) ? 1 : 0;
    int k = threadIdx.x;
    if (k < 16) {
        float s = 0.f;
        for (int h = 0; h < HH; h++) s += We1[k * HH + h] * ae1[h];
        g_ve[k] = s;
    } else if (k < 32) {
        int kk = k - 16;
        float s = 0.f;
        for (int h = 0; h < HH; h++) s += We2[kk * HH + h] * ae2[h];
        g_ve[16 + kk] = s;
    }
}

__global__ void k_edges(const int* __restrict__ ei_raw, const float* __restrict__ ea) {
    __shared__ float sve[32];
    if (threadIdx.x < 32) sve[threadIdx.x] = g_ve[threadIdx.x];
    __syncthreads();
    int stride = gridDim.x * blockDim.x;
    int idx64 = g_idx64;
    for (int e = blockIdx.x * blockDim.x + threadIdx.x; e < EE; e += stride) {
        int src, dst;
        if (idx64) {
            const long long* pp = (const long long*)ei_raw;
            src = (int)pp[e]; dst = (int)pp[EE + e];
        } else {
            src = ei_raw[e]; dst = ei_raw[EE + e];
        }
        g_src[e] = src; g_dst[e] = dst;
        const float* eav = ea + (size_t)e * 16;
        float t1 = 0.f, t2 = 0.f;
#pragma unroll
        for (int q = 0; q < 16; q++) {
            float v = eav[q];
            t1 += v * sve[q];
            t2 += v * sve[16 + q];
        }
        g_eterm1[e] = t1; g_eterm2[e] = t2;
        atomicAdd(&g_set1[dst], t1);
        atomicAdd(&g_set2[dst], t2);
        atomicAdd(&g_deg[dst], 1.0f);
    }
}

__global__ void k_loopdiv() {
    int i = blockIdx.x * blockDim.x + threadIdx.x;
    if (i >= NN) return;
    float d = fmaxf(g_deg[i], 1.0f);
    g_set1[i] /= d;
    g_set2[i] /= d;
}

// single-block exclusive prefix sum of deg -> rowptr, cursor
__global__ void __launch_bounds__(1024) k_prefix() {
    __shared__ int sws[32];
    __shared__ int chunk_total;
    int lane = threadIdx.x & 31, wid = threadIdx.x >> 5;
    int running = 0;
    for (int base = 0; base < NN; base += 1024) {
        int i = base + threadIdx.x;
        int v = (i < NN) ? (int)g_deg[i] : 0;
        int x = v;
#pragma unroll
        for (int off = 1; off < 32; off <<= 1) {
            int y = __shfl_up_sync(0xffffffffu, x, off);
            if (lane >= off) x += y;
        }
        if (lane == 31) sws[wid] = x;
        __syncthreads();
        if (wid == 0) {
            int y = sws[lane];
#pragma unroll
            for (int off = 1; off < 32; off <<= 1) {
                int z = __shfl_up_sync(0xffffffffu, y, off);
                if (lane >= off) y += z;
            }
            sws[lane] = y;
            if (lane == 31) chunk_total = y;
        }
        __syncthreads();
        int incl = x + (wid > 0 ? sws[wid - 1] : 0);
        if (i < NN) {
            int excl = running + incl - v;
            g_rowptr[i] = excl;
            g_cursor[i] = excl;
        }
        running += chunk_total;
        __syncthreads();
    }
    if (threadIdx.x == 0) g_rowptr[NN] = running;
}

__global__ void k_scatter() {
    int stride = gridDim.x * blockDim.x;
    for (int e = blockIdx.x * blockDim.x + threadIdx.x; e < EE; e += stride) {
        int dst = g_dst[e];
        int pos = atomicAdd(&g_cursor[dst], 1);
        g_srcs[pos] = g_src[e];
        g_et1s[pos] = g_eterm1[e];
        g_et2s[pos] = g_eterm2[e];
    }
}

// layer 0: g_g[0] = x @ W ;  layer 1: g_g[1] = relu(g_agg[0] + bias) @ W
// Epilogue fused: g_gs/g_gd[layer][row] = row . att_src / att_dst
__global__ void __launch_bounds__(256) k_gemm128(int layer,
                                                 const float* __restrict__ x,
                                                 const float* __restrict__ W,
                                                 const float* __restrict__ bias,
                                                 const float* __restrict__ as,
                                                 const float* __restrict__ ad) {
    __shared__ float4 Ws4[64 * 32];
    const float* A = (layer == 0) ? x : g_agg[0];
    float*       C = g_g[layer];
    int tid  = threadIdx.x;
    int warp = tid >> 5, lane = tid & 31;
    int row0 = blockIdx.x * 32 + warp * 4;

    float4 bsel = make_float4(0.f, 0.f, 0.f, 0.f);
    if (layer == 1) bsel = ((const float4*)bias)[lane];
    float4 as4 = ((const float4*)as)[lane];
    float4 ad4 = ((const float4*)ad)[lane];

    float4 av[4];
#pragma unroll
    for (int r = 0; r < 4; r++) {
        int row = row0 + r;
        float4 v = make_float4(0.f, 0.f, 0.f, 0.f);
        if (row < NN) {
            v = ((const float4*)A)[(size_t)row * 32 + lane];
            if (layer == 1) {
                v.x = relu_np(v.x + bsel.x);
                v.y = relu_np(v.y + bsel.y);
                v.z = relu_np(v.z + bsel.z);
                v.w = relu_np(v.w + bsel.w);
            }
        }
        av[r] = v;
    }

    float4 acc[4];
#pragma unroll
    for (int r = 0; r < 4; r++) acc[r] = make_float4(0.f, 0.f, 0.f, 0.f);

#pragma unroll
    for (int chunk = 0; chunk < 2; chunk++) {
        const float4* Wc = (const float4*)W + chunk * 64 * 32;
        __syncthreads();
        for (int i = tid; i < 64 * 32; i += 256) Ws4[i] = Wc[i];
        __syncthreads();
#pragma unroll
        for (int kk = 0; kk < 64; kk++) {
            int k = chunk * 64 + kk;
            int srcLane = k >> 2;
            const int sel = k & 3;
            float4 w4 = Ws4[kk * 32 + lane];
#pragma unroll
            for (int r = 0; r < 4; r++) {
                float av_sel = (sel == 0) ? av[r].x : (sel == 1) ? av[r].y
                             : (sel == 2) ? av[r].z : av[r].w;
                float a_k = __shfl_sync(0xffffffffu, av_sel, srcLane);
                acc[r].x += a_k * w4.x;
                acc[r].y += a_k * w4.y;
                acc[r].z += a_k * w4.z;
                acc[r].w += a_k * w4.w;
            }
        }
    }

#pragma unroll
    for (int r = 0; r < 4; r++) {
        int row = row0 + r;
        if (row < NN) {
            ((float4*)C)[(size_t)row * 32 + lane] = acc[r];
            float s = acc[r].x * as4.x + acc[r].y * as4.y + acc[r].z * as4.z + acc[r].w * as4.w;
            float d = acc[r].x * ad4.x + acc[r].y * ad4.y + acc[r].z * ad4.z + acc[r].w * ad4.w;
#pragma unroll
            for (int off = 16; off > 0; off >>= 1) {
                s += __shfl_xor_sync(0xffffffffu, s, off);
                d += __shfl_xor_sync(0xffffffffu, d, off);
            }
            if (lane == 0) {
                g_gs[layer][row] = s;
                g_gd[layer][row] = d;
            }
        }
    }
}

// Fused attention softmax + aggregation: one warp per node, ZERO atomics.
__global__ void __launch_bounds__(256) k_aggfused(int layer) {
    int node = blockIdx.x * 8 + (threadIdx.x >> 5);
    int lane = threadIdx.x & 31;
    if (node >= NN) return;
    const float* gs  = g_gs[layer];
    const float* gd  = g_gd[layer];
    const float* ets = layer ? g_et2s : g_et1s;
    const float* set = layer ? g_set2 : g_set1;
    const float* gp  = g_g[layer];
    float* aggp      = g_agg[layer];

    int beg = g_rowptr[node], end = g_rowptr[node + 1];
    float gd_i = gd[node];

    // self-loop alpha (identical on all lanes)
    float a_self = gs[node] + gd_i + set[node];
    a_self = a_self > 0.f ? a_self : 0.2f * a_self;
    float ex_self = expf(a_self);

    // pass 1: per-edge ex + den
    float densum = 0.f;
    for (int j = beg + lane; j < end; j += 32) {
        int src = g_srcs[j];
        float a = gs[src] + gd_i + ets[j];
        a = a > 0.f ? a : 0.2f * a;
        float ex = expf(a);
        g_ex[j] = ex;
        densum += ex;
    }
#pragma unroll
    for (int off = 16; off > 0; off >>= 1)
        densum += __shfl_xor_sync(0xffffffffu, densum, off);
    float inv = 1.0f / (densum + ex_self);

    // pass 2: weighted gather-accumulate (full warp per edge)
    float w = ex_self * inv;
    float4 v = *(const float4*)(gp + (size_t)node * HH + lane * 4);
    float4 acc = make_float4(w * v.x, w * v.y, w * v.z, w * v.w);
    for (int j = beg; j < end; j++) {
        float wj = g_ex[j] * inv;       // broadcast load
        int src  = g_srcs[j];           // broadcast load
        float4 u = *(const float4*)(gp + (size_t)src * HH + lane * 4);
        acc.x += wj * u.x;
        acc.y += wj * u.y;
        acc.z += wj * u.z;
        acc.w += wj * u.w;
    }
    *(float4*)(aggp + (size_t)node * HH + lane * 4) = acc;
}

__global__ void k_hgsum(const float* __restrict__ b2) {
    __shared__ float sh[HH];
    int c = threadIdx.x & 127;
    int half = threadIdx.x >> 7;
    float bb = b2[c];
    float s = 0.f;
    for (int i = blockIdx.x * 2 + half; i < NN; i += gridDim.x * 2)
        s += relu_np(g_agg[1][(size_t)i * HH + c] + bb);
    if (half == 1) sh[c] = s;
    __syncthreads();
    if (half == 0) g_hpart[blockIdx.x * HH + c] = s + sh[c];
}

__global__ void k_head(const float* __restrict__ muW, const float* __restrict__ mub,
                       const float* __restrict__ lvW, const float* __restrict__ lvb,
                       const float* __restrict__ eps,
                       const float* __restrict__ decW, const float* __restrict__ decb,
                       const float* __restrict__ aW1, const float* __restrict__ ab1,
                       const float* __restrict__ aW2, const float* __restrict__ ab2,
                       const float* __restrict__ nW1, const float* __restrict__ nb1,
                       const float* __restrict__ nW2, const float* __restrict__ nb2,
                       float* __restrict__ out) {
    __shared__ float hgm[HH], z[LATD], hd[HH], tmp[HH];
    int t = threadIdx.x;
    if (t < HH) {
        float s = 0.f;
        for (int b = 0; b < HG_BLOCKS; b++) s += g_hpart[b * HH + t];
        hgm[t] = s * (1.0f / (float)NN);
    }
    __syncthreads();
    if (t < LATD) {
        float m = mub[t], l = lvb[t];
        for (int k = 0; k < HH; k++) { m += hgm[k] * muW[k * LATD + t]; l += hgm[k] * lvW[k * LATD + t]; }
        out[MU_OFF + t] = m;
        out[LV_OFF + t] = l;
        z[t] = m + eps[t] * expf(0.5f * l);
    }
    __syncthreads();
    if (t < HH) {
        float s = decb[t];
        for (int j = 0; j < LATD; j++) s += z[j] * decW[j * HH + t];
        hd[t] = relu_np(s);
    }
    __syncthreads();
    if (t < HH) {
        float s = ab1[t];
        for (int k = 0; k < HH; k++) s += hd[k] * aW1[k * HH + t];
        tmp[t] = relu_np(s);
    }
    __syncthreads();
    for (int m = t; m < MAXNODE; m += blockDim.x) {
        float s = ab2[m];
        for (int k = 0; k < HH; k++) s += tmp[k] * aW2[k * MAXNODE + m];
        g_adj_row[m] = s;
    }
    __syncthreads();
    if (t < HH) {
        float s = nb1[t];
        for (int k = 0; k < HH; k++) s += hd[k] * nW1[k * HH + t];
        tmp[t] = relu_np(s);
    }
    __syncthreads();
    if (t < HH) {
        float s = nb2[t];
        for (int k = 0; k < HH; k++) s += tmp[k] * nW2[k * HH + t];
        g_node_row[t] = s;
    }
}

__global__ void k_fill(float4* __restrict__ out4) {
    __shared__ float4 sadj[50];
    __shared__ float4 snd[32];
    int t = threadIdx.x;
    if (t < 50) sadj[t] = ((const float4*)g_adj_row)[t];
    else if (t < 82) snd[t - 50] = ((const float4*)g_node_row)[t - 50];
    __syncthreads();
    const int ADJ4 = ADJ_SZ / 4;
    const int TOT4 = (ADJ_SZ + NODES_SZ) / 4;
    int stride = gridDim.x * blockDim.x;
    for (int i = blockIdx.x * blockDim.x + t; i < TOT4; i += stride) {
        float4 v;
        if (i < ADJ4) v = sadj[i % 50];
        else          v = snd[(i - ADJ4) & 31];
        out4[i] = v;
    }
}

extern "C" void kernel_launch(void* const* d_in, const int* in_sizes, int n_in,
                              void* d_out, int out_size) {
    const float* x   = (const float*)d_in[0];
    const int*   ei  = (const int*)  d_in[1];
    const float* ea  = (const float*)d_in[2];
    const float* eps = (const float*)d_in[3];
    int p = n_in - 26;
    if (p < 4) p = 4;
    if (p > 5) p = (in_sizes[4] == 1) ? 5 : 4;
    const float* W1   = (const float*)d_in[p + 0];
    const float* as1  = (const float*)d_in[p + 1];
    const float* ad1  = (const float*)d_in[p + 2];
    const float* We1  = (const float*)d_in[p + 3];
    const float* ae1  = (const float*)d_in[p + 4];
    const float* b1   = (const float*)d_in[p + 5];
    const float* W2   = (const float*)d_in[p + 6];
    const float* as2  = (const float*)d_in[p + 7];
    const float* ad2  = (const float*)d_in[p + 8];
    const float* We2  = (const float*)d_in[p + 9];
    const float* ae2  = (const float*)d_in[p + 10];
    const float* b2   = (const float*)d_in[p + 11];
    const float* muW  = (const float*)d_in[p + 12];
    const float* mub  = (const float*)d_in[p + 13];
    const float* lvW  = (const float*)d_in[p + 14];
    const float* lvb  = (const float*)d_in[p + 15];
    const float* decW = (const float*)d_in[p + 16];
    const float* decb = (const float*)d_in[p + 17];
    const float* aW1  = (const float*)d_in[p + 18];
    const float* ab1  = (const float*)d_in[p + 19];
    const float* aW2  = (const float*)d_in[p + 20];
    const float* ab2  = (const float*)d_in[p + 21];
    const float* nW1  = (const float*)d_in[p + 22];
    const float* nb1  = (const float*)d_in[p + 23];
    const float* nW2  = (const float*)d_in[p + 24];
    const float* nb2  = (const float*)d_in[p + 25];
    float* out = (float*)d_out;

    k_zero<<<256, 256>>>();
    k_pre<<<1, 256>>>(ei, We1, ae1, We2, ae2);
    k_edges<<<2048, 256>>>(ei, ea);
    k_loopdiv<<<(NN + 255) / 256, 256>>>();
    k_prefix<<<1, 1024>>>();
    k_scatter<<<2048, 256>>>();

    int gemm_blocks = (NN + 31) / 32;
    int agg_blocks = (NN + 7) / 8;

    k_gemm128<<<gemm_blocks, 256>>>(0, x, W1, b1, as1, ad1);
    k_aggfused<<<agg_blocks, 256>>>(0);

    k_gemm128<<<gemm_blocks, 256>>>(1, x, W2, b1, as2, ad2);
    k_aggfused<<<agg_blocks, 256>>>(1);

    k_hgsum<<<HG_BLOCKS, 256>>>(b2);
    k_head<<<1, 256>>>(muW, mub, lvW, lvb, eps, decW, decb,
                       aW1, ab1, aW2, ab2, nW1, nb1, nW2, nb2, out);
    k_fill<<<2048, 256>>>((float4*)out);
}